// round 8
// baseline (speedup 1.0000x reference)
#include <cuda_runtime.h>
#include <cstdint>

#define HID   64
#define CHUNK 128
#define SEQS  4      // sequences per CTA
#define NTHR  256    // tid = e*4 + kh*2 + od  (k-split x2)
#define NBLK  256    // 256 * 4 = 1024 sequences

typedef unsigned long long ull;

__device__ __forceinline__ ull pk2(float a, float b) {
    ull r; asm("mov.b64 %0, {%1, %2};" : "=l"(r) : "f"(a), "f"(b)); return r;
}
__device__ __forceinline__ void upk2(ull v, float &a, float &b) {
    asm("mov.b64 {%0, %1}, %2;" : "=f"(a), "=f"(b) : "l"(v));
}
__device__ __forceinline__ ull ffma2(ull a, ull b, ull c) {
    ull d; asm("fma.rn.f32x2 %0, %1, %2, %3;" : "=l"(d) : "l"(a), "l"(b), "l"(c)); return d;
}
// single-MUFU tanh (sm_75+): MUFU.TANH
__device__ __forceinline__ float ftanh_(float x){
    float y; asm("tanh.approx.f32 %0, %1;" : "=f"(y) : "f"(x)); return y;
}
// sigmoid(x) = 0.5*tanh(0.5x) + 0.5  -> 1 MUL + 1 MUFU + 1 FMA
__device__ __forceinline__ float fsig(float x){
    return fmaf(0.5f, ftanh_(0.5f * x), 0.5f);
}

__global__ void pc_zero_kernel(float* o) { if (threadIdx.x == 0) o[0] = 0.0f; }

__global__ void __launch_bounds__(NTHR, 2)
pc_lstm_kernel(const int*   __restrict__ inds,
               const float* __restrict__ p,
               const float* __restrict__ ls_probs,
               const float* __restrict__ open_probs,
               const int*   __restrict__ open_slices,
               const float* __restrict__ open_hx,
               const float* __restrict__ W_ih,
               const float* __restrict__ W_hh,
               const float* __restrict__ b_ih,
               const float* __restrict__ b_hh,
               const float* __restrict__ W_out,
               const float* __restrict__ b_out,
               const int*   __restrict__ n_chunks_ptr,
               float*       __restrict__ out)
{
    // double-buffered h, stored UNSPLATTED: 64 plain floats per seq
    __shared__ __align__(16) float hspF[2][SEQS][HID];
    __shared__ __align__(16) ull   xsh[SEQS][CHUNK][2];   // splatted (x0,x0),(x1,x1)
    __shared__ float  paysh[SEQS][CHUNK];
    __shared__ float  opwSh[SEQS];
    __shared__ float2 olpSh[SEQS];
    __shared__ int    baseSh[SEQS];

    const int tid  = threadIdx.x;
    const int e    = tid >> 2;          // element 0..63
    const int kh   = (tid >> 1) & 1;    // k-half: owns k in [kh*32, kh*32+32)
    const int od   = tid & 1;           // 0: rows (i_e, g_e); 1: rows (f_e, o_e)
    const int w    = tid >> 5;          // warp index; warps 0..3 <-> seqs 0..3 in phase 4
    const int lane = tid & 31;
    const int rowA = e + od * 64;          // i_e or f_e
    const int rowB = e + 128 + od * 64;    // g_e or o_e
    const int kb   = kh * 32;              // k-base for this thread

    // ---- W_hh register-resident, k-half + k-pair packed: 2 rows x 16 f32x2 = 64 regs ----
    ull wregA[16], wregB[16];
    #pragma unroll
    for (int k2 = 0; k2 < 16; ++k2) {
        wregA[k2] = pk2(W_hh[rowA * HID + kb + 2 * k2], W_hh[rowA * HID + kb + 2 * k2 + 1]);
        wregB[k2] = pk2(W_hh[rowB * HID + kb + 2 * k2], W_hh[rowB * HID + kb + 2 * k2 + 1]);
    }

    const ull biasP = pk2(b_ih[rowA] + b_hh[rowA], b_ih[rowB] + b_hh[rowB]);
    const ull wih0  = pk2(W_ih[rowA * 2 + 0], W_ih[rowB * 2 + 0]);
    const ull wih1  = pk2(W_ih[rowA * 2 + 1], W_ih[rowB * 2 + 1]);

    const float wo0 = W_out[2 * lane];
    const float wo1 = W_out[2 * lane + 1];
    const float bo  = b_out[0];

    if (tid < SEQS) {
        int q = blockIdx.x * SEQS + tid;        // global sequence id
        baseSh[tid] = inds[q >> 4] + (q & 15);  // inds[a] + b  (B2 == 16)
        int sl = open_slices[q];
        olpSh[tid] = make_float2(__logf(p[2 * sl]), __logf(p[2 * sl + 1]));
        opwSh[tid] = open_probs[q] * (2.0f * ls_probs[q] - 1.0f);
    }

    // init c (redundant across od,kh) and h (one thread per e publishes)
    float cst[SEQS];
    #pragma unroll
    for (int s = 0; s < SEQS; ++s) {
        int q = blockIdx.x * SEQS + s;
        cst[s] = open_hx[(q * 2 + 1) * HID + e];
        if ((tid & 3) == 0) hspF[0][s][e] = open_hx[(q * 2 + 0) * HID + e];
    }
    __syncthreads();

    const int nch = n_chunks_ptr ? n_chunks_ptr[0] : 128;

    float  nd = 1.0f;           // survival prob chain (warps 0..3, redundant per lane)
    double lossAcc = 0.0;
    int    cur = 0;             // 128 steps/chunk (even) -> cur == 0 at every chunk start

    for (int ch = 0; ch < nch; ++ch) {
        __syncthreads();  // xsh/paysh of previous chunk fully consumed
        // ---- chunk preamble: inputs + payoff precompute ----
        for (int i = tid; i < SEQS * CHUNK; i += NTHR) {
            int s  = i >> 7;
            int tt = i & (CHUNK - 1);
            int b  = baseSh[s] + ch * CHUNK;
            float2 pv = ((const float2*)p)[b + tt];
            float2 pz = ((const float2*)p)[b];
            float x0 = pv.x - pz.x, x1 = pv.y - pz.y;
            xsh[s][tt][0] = pk2(x0, x0);
            xsh[s][tt][1] = pk2(x1, x1);
            paysh[s][tt] = opwSh[s] * ((__logf(pv.x) - olpSh[s].x) + (__logf(pv.y) - olpSh[s].y));
        }
        __syncthreads();

        #pragma unroll 1
        for (int t = 0; t < CHUNK; ++t) {
            // ---- lagged phase 4 h read: issue the LDS early (warps 0..3 only) ----
            float2 hv;
            if (t && w < SEQS) hv = *(const float2*)&hspF[cur][w][2 * lane];

            // ---- input term first: its LDS hides under the matvec issue stream ----
            ull accI[SEQS];
            #pragma unroll
            for (int s = 0; s < SEQS; ++s) {
                ulonglong2 xv = *(const ulonglong2*)&xsh[s][t][0];
                accI[s] = ffma2(wih1, xv.y, ffma2(wih0, xv.x, biasP));
            }

            // ---- phase 1: k-half matvec, h unsplatted, W in regs ----
            ull accA[SEQS], accB[SEQS];
            #pragma unroll
            for (int s = 0; s < SEQS; ++s) { accA[s] = 0ull; accB[s] = 0ull; }
            #pragma unroll
            for (int k4 = 0; k4 < 8; ++k4) {          // 8 iters: 16B LDS -> 4 h values
                #pragma unroll
                for (int s = 0; s < SEQS; ++s) {
                    ulonglong2 hh = *(const ulonglong2*)&hspF[cur][s][kb + 4 * k4];
                    accA[s] = ffma2(wregA[2 * k4],     hh.x, accA[s]);
                    accB[s] = ffma2(wregB[2 * k4],     hh.x, accB[s]);
                    accA[s] = ffma2(wregA[2 * k4 + 1], hh.y, accA[s]);
                    accB[s] = ffma2(wregB[2 * k4 + 1], hh.y, accB[s]);
                }
            }

            // ---- lagged phase 4 (step t-1): warps 0..3, overlaps the FMA stream ----
            if (t && w < SEQS) {
                float part = fmaf(hv.x, wo0, hv.y * wo1);
                #pragma unroll
                for (int o = 16; o; o >>= 1)
                    part += __shfl_xor_sync(0xffffffffu, part, o);
                float raw = fsig(part + bo);
                float pay = paysh[w][t - 1];
                float adj = (t - 1 == 0) ? raw : raw * nd;
                lossAcc += (double)(adj * pay);
                nd *= (1.0f - raw);          // t-1 <= 126 here: always update
            }

            // ---- phase 2+3: fold, k-half reduce, gate exchange, c/h update ----
            #pragma unroll
            for (int s = 0; s < SEQS; ++s) {
                float inA, inB, lA, hA, lB, hB;
                upk2(accI[s], inA, inB);
                upk2(accA[s], lA, hA);
                upk2(accB[s], lB, hB);
                float pA = lA + hA;            // this thread's k-half partial, rowA
                float pB = lB + hB;            // rowB
                pA += __shfl_xor_sync(0xffffffffu, pA, 2);   // combine k-halves
                pB += __shfl_xor_sync(0xffffffffu, pB, 2);
                float a0 = pA + inA;           // pre-activation of rowA (i or f)
                float a1 = pB + inB;           // pre-activation of rowB (g or o)
                float b0 = __shfl_xor_sync(0xffffffffu, a0, 1);
                float b1 = __shfl_xor_sync(0xffffffffu, a1, 1);
                float ipre = od ? b0 : a0;     // SELs, no divergence
                float gpre = od ? b1 : a1;
                float fpre = od ? a0 : b0;
                float opre = od ? a1 : b1;
                float si = fsig(ipre), sf = fsig(fpre);
                float tg = ftanh_(gpre), so = fsig(opre);
                cst[s] = sf * cst[s] + si * tg;
                float h = so * ftanh_(cst[s]);
                if ((tid & 3) == 0) hspF[cur ^ 1][s][e] = h;
            }
            __syncthreads();   // single barrier per step: h published, buffers rotated
            cur ^= 1;
        }

        // ---- trailing phase 4 for t = CHUNK-1 (before preamble overwrites paysh) ----
        if (w < SEQS) {
            float2 hv = *(const float2*)&hspF[cur][w][2 * lane];
            float part = fmaf(hv.x, wo0, hv.y * wo1);
            #pragma unroll
            for (int o = 16; o; o >>= 1)
                part += __shfl_xor_sync(0xffffffffu, part, o);
            float raw = fsig(part + bo);
            float pay = paysh[w][CHUNK - 1];
            lossAcc += (double)(raw * nd * pay);
            // last element of chunk: nd NOT updated (matches cumprod over [:-1])
        }
    }

    if (lane == 0 && w < SEQS) atomicAdd(out, (float)lossAcc);
}

extern "C" void kernel_launch(void* const* d_in, const int* in_sizes, int n_in,
                              void* d_out, int out_size)
{
    const int*   inds        = (const int*)  d_in[0];
    const float* p           = (const float*)d_in[1];
    const float* ls_probs    = (const float*)d_in[2];
    const float* open_probs  = (const float*)d_in[3];
    const int*   open_slices = (const int*)  d_in[4];
    const float* open_hx     = (const float*)d_in[5];
    const float* W_ih        = (const float*)d_in[6];
    const float* W_hh        = (const float*)d_in[7];
    const float* b_ih        = (const float*)d_in[8];
    const float* b_hh        = (const float*)d_in[9];
    const float* W_out       = (const float*)d_in[10];
    const float* b_out       = (const float*)d_in[11];
    const int*   n_chunks    = (n_in > 12) ? (const int*)d_in[12] : nullptr;

    float* out = (float*)d_out;

    pc_zero_kernel<<<1, 32>>>(out);
    pc_lstm_kernel<<<NBLK, NTHR>>>(inds, p, ls_probs, open_probs, open_slices,
                                   open_hx, W_ih, W_hh, b_ih, b_hh,
                                   W_out, b_out, n_chunks, out);
}

// round 9
// speedup vs baseline: 1.1628x; 1.1628x over previous
#include <cuda_runtime.h>
#include <cstdint>

#define HID   64
#define CHUNK 128
#define SEQS  4      // sequences per CTA
#define NTHR  256    // one gate-row per thread
#define NBLK  256    // 256 * 4 = 1024 sequences

typedef unsigned long long ull;

__device__ __forceinline__ ull pk2(float a, float b) {
    ull r; asm("mov.b64 %0, {%1, %2};" : "=l"(r) : "f"(a), "f"(b)); return r;
}
__device__ __forceinline__ void upk2(ull v, float &a, float &b) {
    asm("mov.b64 {%0, %1}, %2;" : "=f"(a), "=f"(b) : "l"(v));
}
__device__ __forceinline__ ull ffma2(ull a, ull b, ull c) {
    ull d; asm("fma.rn.f32x2 %0, %1, %2, %3;" : "=l"(d) : "l"(a), "l"(b), "l"(c)); return d;
}
// single-MUFU tanh (sm_75+): MUFU.TANH
__device__ __forceinline__ float ftanh_(float x){
    float y; asm("tanh.approx.f32 %0, %1;" : "=f"(y) : "f"(x)); return y;
}
// sigmoid(x) = 0.5*tanh(0.5x) + 0.5
__device__ __forceinline__ float fsig(float x){
    return fmaf(0.5f, ftanh_(0.5f * x), 0.5f);
}

__global__ void pc_zero_kernel(float* o) { if (threadIdx.x == 0) o[0] = 0.0f; }

__global__ void __launch_bounds__(NTHR, 2)
pc_lstm_kernel(const int*   __restrict__ inds,
               const float* __restrict__ p,
               const float* __restrict__ ls_probs,
               const float* __restrict__ open_probs,
               const int*   __restrict__ open_slices,
               const float* __restrict__ open_hx,
               const float* __restrict__ W_ih,
               const float* __restrict__ W_hh,
               const float* __restrict__ b_ih,
               const float* __restrict__ b_hh,
               const float* __restrict__ W_out,
               const float* __restrict__ b_out,
               const int*   __restrict__ n_chunks_ptr,
               float*       __restrict__ out)
{
    __shared__ __align__(16) float  hspF[SEQS][HID];         // h state (single buffer)
    __shared__ __align__(16) float  gsm[SEQS][HID][4];       // pre-acts [s][e][gate]
    __shared__ __align__(16) float2 xsh2[SEQS][CHUNK];       // (x0,x1)
    __shared__ float  paysh[SEQS][CHUNK];
    __shared__ float  opwSh[SEQS];
    __shared__ float2 olpSh[SEQS];
    __shared__ int    baseSh[SEQS];

    const int tid  = threadIdx.x;
    const int w    = tid >> 5;          // warp 0..7
    const int lane = tid & 31;

    // ---- matvec role: one W_hh row per thread ----
    const int me  = 8 * w + (lane & 7);   // element 0..63
    const int mg  = lane >> 3;            // gate 0..3 (i,f,g,o)
    const int row = mg * 64 + me;         // W_hh row

    ull wreg[32];                          // 64 k-values, k-pair packed
    #pragma unroll
    for (int k2 = 0; k2 < 32; ++k2)
        wreg[k2] = pk2(W_hh[row * HID + 2 * k2], W_hh[row * HID + 2 * k2 + 1]);
    const float bias = b_ih[row] + b_hh[row];
    const float wi0  = W_ih[row * 2 + 0];
    const float wi1  = W_ih[row * 2 + 1];

    // ---- gate role: one (seq, element) per thread ----
    const int gs = tid >> 6;              // seq 0..3
    const int ge = tid & 63;              // element 0..63

    // ---- phase-4 role: warps 0..3 <-> seqs ----
    const float wo0 = W_out[2 * lane];
    const float wo1 = W_out[2 * lane + 1];
    const float bo  = b_out[0];

    if (tid < SEQS) {
        int q = blockIdx.x * SEQS + tid;
        baseSh[tid] = inds[q >> 4] + (q & 15);   // B2 == 16
        int sl = open_slices[q];
        olpSh[tid] = make_float2(__logf(p[2 * sl]), __logf(p[2 * sl + 1]));
        opwSh[tid] = open_probs[q] * (2.0f * ls_probs[q] - 1.0f);
    }

    // init c (gate-role thread owns exactly one) and h
    float cc;
    {
        int q = blockIdx.x * SEQS + gs;
        cc = open_hx[(q * 2 + 1) * HID + ge];
        hspF[gs][ge] = open_hx[(q * 2 + 0) * HID + ge];
    }
    __syncthreads();

    const int nch = n_chunks_ptr ? n_chunks_ptr[0] : 128;

    float  nd = 1.0f;            // survival chain (warps 0..3, redundant per lane)
    double lossAcc = 0.0;

    for (int ch = 0; ch < nch; ++ch) {
        __syncthreads();  // previous chunk's paysh/xsh fully consumed
        // ---- chunk preamble ----
        for (int i = tid; i < SEQS * CHUNK; i += NTHR) {
            int s  = i >> 7;
            int tt = i & (CHUNK - 1);
            int b  = baseSh[s] + ch * CHUNK;
            float2 pv = ((const float2*)p)[b + tt];
            float2 pz = ((const float2*)p)[b];
            xsh2[s][tt] = make_float2(pv.x - pz.x, pv.y - pz.y);
            paysh[s][tt] = opwSh[s] * ((__logf(pv.x) - olpSh[s].x) + (__logf(pv.y) - olpSh[s].y));
        }
        __syncthreads();

        #pragma unroll 1
        for (int t = 0; t < CHUNK; ++t) {
            // ---- lagged phase-4 h read (h of step t-1), before any overwrite ----
            float2 hv;
            if (t && w < SEQS) hv = ((const float2*)hspF[w])[lane];

            // ---- input term (scalar per row per seq) ----
            float accI[SEQS];
            #pragma unroll
            for (int s = 0; s < SEQS; ++s) {
                float2 xv = xsh2[s][t];
                accI[s] = fmaf(wi1, xv.y, fmaf(wi0, xv.x, bias));
            }

            // ---- matvec: one row x 4 seqs, 32 ffma2 each ----
            ull acc[SEQS];
            #pragma unroll
            for (int s = 0; s < SEQS; ++s) acc[s] = 0ull;
            #pragma unroll
            for (int k4 = 0; k4 < 16; ++k4) {
                #pragma unroll
                for (int s = 0; s < SEQS; ++s) {
                    ulonglong2 hh = *(const ulonglong2*)&hspF[s][4 * k4];
                    acc[s] = ffma2(wreg[2 * k4],     hh.x, acc[s]);
                    acc[s] = ffma2(wreg[2 * k4 + 1], hh.y, acc[s]);
                }
            }

            // ---- lagged phase 4 (step t-1), overlaps the FMA stream ----
            if (t && w < SEQS) {
                float part = fmaf(hv.x, wo0, hv.y * wo1);
                #pragma unroll
                for (int o = 16; o; o >>= 1)
                    part += __shfl_xor_sync(0xffffffffu, part, o);
                float raw = fsig(part + bo);
                float pay = paysh[w][t - 1];
                float adj = (t - 1 == 0) ? raw : raw * nd;
                lossAcc += (double)(adj * pay);
                nd *= (1.0f - raw);          // t-1 <= 126: always update
            }

            // ---- publish pre-activations (conflict-free transpose) ----
            #pragma unroll
            for (int s = 0; s < SEQS; ++s) {
                float lo, hi;
                upk2(acc[s], lo, hi);
                gsm[s][me][mg] = (lo + hi) + accI[s];
            }
            __syncthreads();   // BAR1: gsm ready; all h reads of this step done

            // ---- gate phase: one (seq, element) per thread, zero redundancy ----
            {
                float4 gv = *(const float4*)&gsm[gs][ge][0];   // (i,f,g,o)
                float si = fsig(gv.x), sf = fsig(gv.y);
                float tg = ftanh_(gv.z), so = fsig(gv.w);
                cc = sf * cc + si * tg;
                float h = so * ftanh_(cc);
                hspF[gs][ge] = h;
            }
            __syncthreads();   // BAR2: new h visible
        }

        // ---- trailing phase 4 for t = CHUNK-1 ----
        if (w < SEQS) {
            float2 hv = ((const float2*)hspF[w])[lane];
            float part = fmaf(hv.x, wo0, hv.y * wo1);
            #pragma unroll
            for (int o = 16; o; o >>= 1)
                part += __shfl_xor_sync(0xffffffffu, part, o);
            float raw = fsig(part + bo);
            float pay = paysh[w][CHUNK - 1];
            lossAcc += (double)(raw * nd * pay);
            // last element of chunk: nd NOT updated (cumprod over [:-1])
        }
    }

    if (w < SEQS && lane == 0) atomicAdd(out, (float)lossAcc);
}

extern "C" void kernel_launch(void* const* d_in, const int* in_sizes, int n_in,
                              void* d_out, int out_size)
{
    const int*   inds        = (const int*)  d_in[0];
    const float* p           = (const float*)d_in[1];
    const float* ls_probs    = (const float*)d_in[2];
    const float* open_probs  = (const float*)d_in[3];
    const int*   open_slices = (const int*)  d_in[4];
    const float* open_hx     = (const float*)d_in[5];
    const float* W_ih        = (const float*)d_in[6];
    const float* W_hh        = (const float*)d_in[7];
    const float* b_ih        = (const float*)d_in[8];
    const float* b_hh        = (const float*)d_in[9];
    const float* W_out       = (const float*)d_in[10];
    const float* b_out       = (const float*)d_in[11];
    const int*   n_chunks    = (n_in > 12) ? (const int*)d_in[12] : nullptr;

    float* out = (float*)d_out;

    pc_zero_kernel<<<1, 32>>>(out);
    pc_lstm_kernel<<<NBLK, NTHR>>>(inds, p, ls_probs, open_probs, open_slices,
                                   open_hx, W_ih, W_hh, b_ih, b_hh,
                                   W_out, b_out, n_chunks, out);
}

// round 10
// speedup vs baseline: 1.4210x; 1.2221x over previous
#include <cuda_runtime.h>
#include <cstdint>

#define HID   64
#define CHUNK 128
#define SEQS  4      // sequences per CTA
#define NTHR  128    // thread = (e, kh): 64 elements x 2 k-halves
#define NBLK  256    // 256 * 4 = 1024 sequences

typedef unsigned long long ull;

__device__ __forceinline__ ull pk2(float a, float b) {
    ull r; asm("mov.b64 %0, {%1, %2};" : "=l"(r) : "f"(a), "f"(b)); return r;
}
__device__ __forceinline__ void upk2(ull v, float &a, float &b) {
    asm("mov.b64 {%0, %1}, %2;" : "=f"(a), "=f"(b) : "l"(v));
}
__device__ __forceinline__ ull ffma2(ull a, ull b, ull c) {
    ull d; asm("fma.rn.f32x2 %0, %1, %2, %3;" : "=l"(d) : "l"(a), "l"(b), "l"(c)); return d;
}
// single-MUFU tanh (sm_75+): MUFU.TANH
__device__ __forceinline__ float ftanh_(float x){
    float y; asm("tanh.approx.f32 %0, %1;" : "=f"(y) : "f"(x)); return y;
}
// sigmoid(x) = 0.5*tanh(0.5x) + 0.5
__device__ __forceinline__ float fsig(float x){
    return fmaf(0.5f, ftanh_(0.5f * x), 0.5f);
}

__global__ void pc_zero_kernel(float* o) { if (threadIdx.x == 0) o[0] = 0.0f; }

__global__ void __launch_bounds__(NTHR, 2)
pc_lstm_kernel(const int*   __restrict__ inds,
               const float* __restrict__ p,
               const float* __restrict__ ls_probs,
               const float* __restrict__ open_probs,
               const int*   __restrict__ open_slices,
               const float* __restrict__ open_hx,
               const float* __restrict__ W_ih,
               const float* __restrict__ W_hh,
               const float* __restrict__ b_ih,
               const float* __restrict__ b_hh,
               const float* __restrict__ W_out,
               const float* __restrict__ b_out,
               const int*   __restrict__ n_chunks_ptr,
               float*       __restrict__ out)
{
    __shared__ __align__(16) float hspF[2][SEQS][HID];     // double-buffered h
    __shared__ __align__(16) ull   xsh[SEQS][CHUNK][2];    // splatted (x0,x0),(x1,x1)
    __shared__ float  paysh[SEQS][CHUNK];
    __shared__ float  opwSh[SEQS];
    __shared__ float2 olpSh[SEQS];
    __shared__ int    baseSh[SEQS];

    const int tid  = threadIdx.x;
    const int e    = tid >> 1;        // element 0..63
    const int kh   = tid & 1;         // k-half
    const int kb   = kh * 32;         // k base
    const int kh4  = kh << 2;         // XOR constant for bank-spread iteration order
    const int w    = tid >> 5;        // warp 0..3 <-> seq 0..3 in phase 4
    const int lane = tid & 31;

    const int rI = e, rF = 64 + e, rG = 128 + e, rO = 192 + e;

    // ---- W_hh: 4 rows x 32 k-values, k-pair packed, kh=1 rows in i^4 order ----
    ull wI[16], wF[16], wG[16], wO[16];
    #pragma unroll
    for (int i = 0; i < 8; ++i) {
        int kf = kb + 4 * (i ^ kh4);
        wI[2*i]   = pk2(W_hh[rI * HID + kf],     W_hh[rI * HID + kf + 1]);
        wI[2*i+1] = pk2(W_hh[rI * HID + kf + 2], W_hh[rI * HID + kf + 3]);
        wF[2*i]   = pk2(W_hh[rF * HID + kf],     W_hh[rF * HID + kf + 1]);
        wF[2*i+1] = pk2(W_hh[rF * HID + kf + 2], W_hh[rF * HID + kf + 3]);
        wG[2*i]   = pk2(W_hh[rG * HID + kf],     W_hh[rG * HID + kf + 1]);
        wG[2*i+1] = pk2(W_hh[rG * HID + kf + 2], W_hh[rG * HID + kf + 3]);
        wO[2*i]   = pk2(W_hh[rO * HID + kf],     W_hh[rO * HID + kf + 1]);
        wO[2*i+1] = pk2(W_hh[rO * HID + kf + 2], W_hh[rO * HID + kf + 3]);
    }

    const ull biasIF = pk2(b_ih[rI] + b_hh[rI], b_ih[rF] + b_hh[rF]);
    const ull biasGO = pk2(b_ih[rG] + b_hh[rG], b_ih[rO] + b_hh[rO]);
    const ull wIF0 = pk2(W_ih[rI*2],   W_ih[rF*2]);
    const ull wIF1 = pk2(W_ih[rI*2+1], W_ih[rF*2+1]);
    const ull wGO0 = pk2(W_ih[rG*2],   W_ih[rO*2]);
    const ull wGO1 = pk2(W_ih[rG*2+1], W_ih[rO*2+1]);

    const float wo0 = W_out[2 * lane];
    const float wo1 = W_out[2 * lane + 1];
    const float bo  = b_out[0];

    if (tid < SEQS) {
        int q = blockIdx.x * SEQS + tid;
        baseSh[tid] = inds[q >> 4] + (q & 15);   // B2 == 16
        int sl = open_slices[q];
        olpSh[tid] = make_float2(__logf(p[2 * sl]), __logf(p[2 * sl + 1]));
        opwSh[tid] = open_probs[q] * (2.0f * ls_probs[q] - 1.0f);
    }

    // init c (both kh threads, identical) and h (kh==0 publishes)
    float cc[SEQS];
    #pragma unroll
    for (int s = 0; s < SEQS; ++s) {
        int q = blockIdx.x * SEQS + s;
        cc[s] = open_hx[(q * 2 + 1) * HID + e];
        if (!kh) hspF[0][s][e] = open_hx[(q * 2 + 0) * HID + e];
    }
    __syncthreads();

    const int nch = n_chunks_ptr ? n_chunks_ptr[0] : 128;

    float  nd = 1.0f;            // survival chain (warps 0..3, redundant per lane)
    double lossAcc = 0.0;
    int    cur = 0;              // even #steps/chunk -> cur==0 at chunk starts

    for (int ch = 0; ch < nch; ++ch) {
        __syncthreads();  // previous chunk's xsh/paysh fully consumed
        // ---- chunk preamble ----
        for (int i = tid; i < SEQS * CHUNK; i += NTHR) {
            int s  = i >> 7;
            int tt = i & (CHUNK - 1);
            int b  = baseSh[s] + ch * CHUNK;
            float2 pv = ((const float2*)p)[b + tt];
            float2 pz = ((const float2*)p)[b];
            float x0 = pv.x - pz.x, x1 = pv.y - pz.y;
            xsh[s][tt][0] = pk2(x0, x0);
            xsh[s][tt][1] = pk2(x1, x1);
            paysh[s][tt] = opwSh[s] * ((__logf(pv.x) - olpSh[s].x) + (__logf(pv.y) - olpSh[s].y));
        }
        __syncthreads();

        #pragma unroll 1
        for (int t = 0; t < CHUNK; ++t) {
            // ---- lagged phase-4 h read (h after step t-1) ----
            float2 hv;
            if (t) hv = ((const float2*)hspF[cur][w])[lane];

            // ---- input terms, gate-pair packed (identical across kh pair) ----
            ull aIF[SEQS], aGO[SEQS];
            #pragma unroll
            for (int s = 0; s < SEQS; ++s) {
                ulonglong2 xv = *(const ulonglong2*)&xsh[s][t][0];
                aIF[s] = ffma2(wIF1, xv.y, ffma2(wIF0, xv.x, biasIF));
                aGO[s] = ffma2(wGO1, xv.y, ffma2(wGO0, xv.x, biasGO));
            }

            // ---- matvec: 4 rows, k-half, 1 LDS.128 -> 8 FFMA2 ----
            ull accI[SEQS], accF[SEQS], accG[SEQS], accO[SEQS];
            #pragma unroll
            for (int s = 0; s < SEQS; ++s) { accI[s]=0; accF[s]=0; accG[s]=0; accO[s]=0; }
            #pragma unroll
            for (int i = 0; i < 8; ++i) {
                int kf = kb + 4 * (i ^ kh4);     // bank-spread order for kh=1
                #pragma unroll
                for (int s = 0; s < SEQS; ++s) {
                    ulonglong2 hh = *(const ulonglong2*)&hspF[cur][s][kf];
                    accI[s] = ffma2(wI[2*i], hh.x, accI[s]);
                    accF[s] = ffma2(wF[2*i], hh.x, accF[s]);
                    accG[s] = ffma2(wG[2*i], hh.x, accG[s]);
                    accO[s] = ffma2(wO[2*i], hh.x, accO[s]);
                    accI[s] = ffma2(wI[2*i+1], hh.y, accI[s]);
                    accF[s] = ffma2(wF[2*i+1], hh.y, accF[s]);
                    accG[s] = ffma2(wG[2*i+1], hh.y, accG[s]);
                    accO[s] = ffma2(wO[2*i+1], hh.y, accO[s]);
                }
            }

            // ---- lagged phase 4 (step t-1), overlaps the FMA stream ----
            if (t) {
                float part = fmaf(hv.x, wo0, hv.y * wo1);
                #pragma unroll
                for (int o = 16; o; o >>= 1)
                    part += __shfl_xor_sync(0xffffffffu, part, o);
                float raw = fsig(part + bo);
                float pay = paysh[w][t - 1];
                float adj = (t - 1 == 0) ? raw : raw * nd;
                lossAcc += (double)(adj * pay);
                nd *= (1.0f - raw);          // t-1 <= 126: always update
            }

            // ---- fold, k-half combine, split-MUFU gates, c/h update ----
            #pragma unroll
            for (int s = 0; s < SEQS; ++s) {
                float lo, hi;
                upk2(accI[s], lo, hi); float fIv = lo + hi;
                upk2(accF[s], lo, hi); float fFv = lo + hi;
                upk2(accG[s], lo, hi); float fGv = lo + hi;
                upk2(accO[s], lo, hi); float fOv = lo + hi;
                fIv += __shfl_xor_sync(0xffffffffu, fIv, 1);   // combine k-halves
                fFv += __shfl_xor_sync(0xffffffffu, fFv, 1);
                fGv += __shfl_xor_sync(0xffffffffu, fGv, 1);
                fOv += __shfl_xor_sync(0xffffffffu, fOv, 1);
                float inI, inF, inG, inO;
                upk2(aIF[s], inI, inF);
                upk2(aGO[s], inG, inO);
                float pI = fIv + inI, pF = fFv + inF;
                float pG = fGv + inG, pO = fOv + inO;

                // split MUFU across the kh pair (all via MUFU.TANH):
                // kh0 computes si, sf ; kh1 computes tg, so ; exchange 2 values
                float u1 = kh ? pG : 0.5f * pI;
                float r1 = ftanh_(u1);
                float g1 = kh ? r1 : fmaf(0.5f, r1, 0.5f);     // kh0: si, kh1: tg
                float u2 = 0.5f * (kh ? pO : pF);
                float g2 = fmaf(0.5f, ftanh_(u2), 0.5f);       // kh0: sf, kh1: so
                float x1 = __shfl_xor_sync(0xffffffffu, g1, 1);
                float x2 = __shfl_xor_sync(0xffffffffu, g2, 1);
                float si = kh ? x1 : g1;
                float tg = kh ? g1 : x1;
                float sf = kh ? x2 : g2;
                float so = kh ? g2 : x2;
                cc[s] = sf * cc[s] + si * tg;
                if (!kh) hspF[cur ^ 1][s][e] = so * ftanh_(cc[s]);
            }
            __syncthreads();   // single barrier: h published, buffers rotate
            cur ^= 1;
        }

        // ---- trailing phase 4 for t = CHUNK-1 ----
        {
            float2 hv = ((const float2*)hspF[cur][w])[lane];
            float part = fmaf(hv.x, wo0, hv.y * wo1);
            #pragma unroll
            for (int o = 16; o; o >>= 1)
                part += __shfl_xor_sync(0xffffffffu, part, o);
            float raw = fsig(part + bo);
            float pay = paysh[w][CHUNK - 1];
            lossAcc += (double)(raw * nd * pay);
            // last element of chunk: nd NOT updated (cumprod over [:-1])
        }
    }

    if (lane == 0) atomicAdd(out, (float)lossAcc);
}

extern "C" void kernel_launch(void* const* d_in, const int* in_sizes, int n_in,
                              void* d_out, int out_size)
{
    const int*   inds        = (const int*)  d_in[0];
    const float* p           = (const float*)d_in[1];
    const float* ls_probs    = (const float*)d_in[2];
    const float* open_probs  = (const float*)d_in[3];
    const int*   open_slices = (const int*)  d_in[4];
    const float* open_hx     = (const float*)d_in[5];
    const float* W_ih        = (const float*)d_in[6];
    const float* W_hh        = (const float*)d_in[7];
    const float* b_ih        = (const float*)d_in[8];
    const float* b_hh        = (const float*)d_in[9];
    const float* W_out       = (const float*)d_in[10];
    const float* b_out       = (const float*)d_in[11];
    const int*   n_chunks    = (n_in > 12) ? (const int*)d_in[12] : nullptr;

    float* out = (float*)d_out;

    pc_zero_kernel<<<1, 32>>>(out);
    pc_lstm_kernel<<<NBLK, NTHR>>>(inds, p, ls_probs, open_probs, open_slices,
                                   open_hx, W_ih, W_hh, b_ih, b_hh,
                                   W_out, b_out, n_chunks, out);
}